// round 1
// baseline (speedup 1.0000x reference)
#include <cuda_runtime.h>
#include <cuda_bf16.h>
#include <math.h>

// Problem constants
#define B_SZ 2
#define L_SEQ 1024
#define D_IN 1024
#define D_MODEL 2048
#define D_STATE 16
#define D_DISCR 128
#define KER 4

#define M_ROWS (B_SZ * L_SEQ)          // 2048

// ---------------- scratch (device globals; no allocation) ----------------
__device__ float g_ab[(size_t)M_ROWS * 2 * D_MODEL];   // [b,l,4096] in_proj out
__device__ float g_a[(size_t)M_ROWS * D_MODEL];        // post conv+silu
__device__ float g_Bm[(size_t)M_ROWS * D_STATE];
__device__ float g_Cm[(size_t)M_ROWS * D_STATE];
__device__ float g_t[(size_t)M_ROWS * D_DISCR];        // a @ w_D1^T
__device__ float g_delta[(size_t)M_ROWS * D_MODEL];
__device__ float g_y[(size_t)M_ROWS * D_MODEL];        // pre out-proj

// ---------------- generic NT SGEMM: C[m,n] = sum_k A[m,k] * W[n,k] ----------
// A: M x K row-major, W: N x K row-major, C: M x N row-major.
// EPI: 0 = plain store (or atomicAdd if gridDim.z>1), 1 = softplus(bias[n]+v)
template<int BM, int BN, int BK, int TM, int TN, int EPI>
__global__ __launch_bounds__((BM/TM)*(BN/TN))
void sgemm_nt(int M, int N, int K,
              const float* __restrict__ A,
              const float* __restrict__ W,
              float* __restrict__ C,
              const float* __restrict__ bias,
              int kPerSplit)
{
    constexpr int NTHR = (BM/TM)*(BN/TN);
    __shared__ float As[BK][BM];
    __shared__ float Ws[BK][BN];

    const int tid  = threadIdx.x;
    const int row0 = blockIdx.x * BM;
    const int col0 = blockIdx.y * BN;
    const int k0   = blockIdx.z * kPerSplit;
    const int kEnd = min(K, k0 + kPerSplit);

    // cooperative loaders (float4)
    const int aCol = tid % (BK/4);
    const int aRow = tid / (BK/4);
    constexpr int aStride = NTHR / (BK/4);
    const int wCol = tid % (BK/4);
    const int wRow = tid / (BK/4);
    constexpr int wStride = NTHR / (BK/4);

    const int tRow = (tid / (BN/TN)) * TM;
    const int tCol = (tid % (BN/TN)) * TN;

    float acc[TM][TN];
#pragma unroll
    for (int i = 0; i < TM; i++)
#pragma unroll
        for (int j = 0; j < TN; j++) acc[i][j] = 0.f;

    for (int kt = k0; kt < kEnd; kt += BK) {
#pragma unroll
        for (int i = 0; i < BM; i += aStride) {
            float4 v = *(const float4*)(A + (size_t)(row0 + aRow + i) * K + kt + aCol * 4);
            As[aCol*4 + 0][aRow + i] = v.x;
            As[aCol*4 + 1][aRow + i] = v.y;
            As[aCol*4 + 2][aRow + i] = v.z;
            As[aCol*4 + 3][aRow + i] = v.w;
        }
#pragma unroll
        for (int i = 0; i < BN; i += wStride) {
            float4 v = *(const float4*)(W + (size_t)(col0 + wRow + i) * K + kt + wCol * 4);
            Ws[wCol*4 + 0][wRow + i] = v.x;
            Ws[wCol*4 + 1][wRow + i] = v.y;
            Ws[wCol*4 + 2][wRow + i] = v.z;
            Ws[wCol*4 + 3][wRow + i] = v.w;
        }
        __syncthreads();

#pragma unroll
        for (int kk = 0; kk < BK; kk++) {
            float rm[TM], rn[TN];
#pragma unroll
            for (int i = 0; i < TM; i++) rm[i] = As[kk][tRow + i];
#pragma unroll
            for (int j = 0; j < TN; j++) rn[j] = Ws[kk][tCol + j];
#pragma unroll
            for (int i = 0; i < TM; i++)
#pragma unroll
                for (int j = 0; j < TN; j++) acc[i][j] = fmaf(rm[i], rn[j], acc[i][j]);
        }
        __syncthreads();
    }

    const bool doAtomic = (gridDim.z > 1);
#pragma unroll
    for (int i = 0; i < TM; i++) {
        const int r = row0 + tRow + i;
#pragma unroll
        for (int j = 0; j < TN; j++) {
            const int c = col0 + tCol + j;
            float v = acc[i][j];
            float* dst = C + (size_t)r * N + c;
            if (EPI == 1) {
                float x = bias[c] + v;
                // stable softplus
                float sp = (x > 20.f) ? x : log1pf(expf(x));
                *dst = sp;
            } else {
                if (doAtomic) atomicAdd(dst, v);
                else          *dst = v;
            }
        }
    }
}

// ---------------- depthwise causal conv (ker=4) + bias + SiLU ----------------
__global__ void conv_silu_kernel(const float* __restrict__ ab,
                                 const float* __restrict__ cw,
                                 const float* __restrict__ cb,
                                 float* __restrict__ a_out)
{
    int idx = blockIdx.x * blockDim.x + threadIdx.x;               // over B*L*DM
    if (idx >= B_SZ * L_SEQ * D_MODEL) return;
    int d = idx & (D_MODEL - 1);
    int l = (idx >> 11) & (L_SEQ - 1);
    int b = idx >> 21;

    float w0 = cw[d*4+0], w1 = cw[d*4+1], w2 = cw[d*4+2], w3 = cw[d*4+3];
    const size_t rowBase = ((size_t)b * L_SEQ) * (2*D_MODEL);
    float s = cb[d];
    if (l >= 3) s += w0 * ab[rowBase + (size_t)(l-3)*(2*D_MODEL) + d];
    if (l >= 2) s += w1 * ab[rowBase + (size_t)(l-2)*(2*D_MODEL) + d];
    if (l >= 1) s += w2 * ab[rowBase + (size_t)(l-1)*(2*D_MODEL) + d];
    s += w3 * ab[rowBase + (size_t)l*(2*D_MODEL) + d];
    // silu
    a_out[idx] = s / (1.f + expf(-s));
}

// ---------------- fused SSM scan + output gating ----------------
// thread = one (b,d) channel; 16 states in registers; loop over L.
// y[b,l,d] = (sum_s h_s * Cm[b,l,s] + Dp[d]*a) * silu(gate[b,l,d])
__global__ __launch_bounds__(256)
void scan_kernel(const float* __restrict__ delta,
                 const float* __restrict__ a,
                 const float* __restrict__ ab,   // gate at column offset D_MODEL
                 const float* __restrict__ Bm,
                 const float* __restrict__ Cm,
                 const float* __restrict__ A_param,
                 const float* __restrict__ D_param,
                 float* __restrict__ y)
{
    int gid = blockIdx.x * blockDim.x + threadIdx.x;     // over B*DM = 4096
    if (gid >= B_SZ * D_MODEL) return;
    int b = gid >> 11;
    int d = gid & (D_MODEL - 1);

    float expA[D_STATE];
#pragma unroll
    for (int s = 0; s < D_STATE; s++) expA[s] = expf(-A_param[(size_t)d * D_STATE + s]);
    const float Dp = D_param[d];

    float h[D_STATE];
#pragma unroll
    for (int s = 0; s < D_STATE; s++) h[s] = 0.f;

    const size_t chanBase = (size_t)b * L_SEQ;
    for (int l = 0; l < L_SEQ; l++) {
        const size_t row = chanBase + l;
        const size_t idx = row * D_MODEL + d;
        float dlt = delta[idx];
        float av  = a[idx];
        float g   = ab[row * (2*D_MODEL) + D_MODEL + d];

        const float4* Bp = (const float4*)(Bm + row * D_STATE);
        const float4* Cp = (const float4*)(Cm + row * D_STATE);
        float4 B0 = Bp[0], B1 = Bp[1], B2 = Bp[2], B3 = Bp[3];
        float4 C0 = Cp[0], C1 = Cp[1], C2 = Cp[2], C3 = Cp[3];
        float Bv[16] = {B0.x,B0.y,B0.z,B0.w, B1.x,B1.y,B1.z,B1.w,
                        B2.x,B2.y,B2.z,B2.w, B3.x,B3.y,B3.z,B3.w};
        float Cv[16] = {C0.x,C0.y,C0.z,C0.w, C1.x,C1.y,C1.z,C1.w,
                        C2.x,C2.y,C2.z,C2.w, C3.x,C3.y,C3.z,C3.w};

        float xc = dlt * av;
        float acc = 0.f;
#pragma unroll
        for (int s = 0; s < D_STATE; s++) {
            h[s] = fmaf(expA[s] * dlt, h[s], Bv[s] * xc);
            acc  = fmaf(h[s], Cv[s], acc);
        }
        float silu_g = g / (1.f + expf(-g));
        y[idx] = (acc + Dp * av) * silu_g;
    }
}

// ---------------- launch ----------------
extern "C" void kernel_launch(void* const* d_in, const int* in_sizes, int n_in,
                              void* d_out, int out_size)
{
    const float* seq     = (const float*)d_in[0];
    const float* w_in    = (const float*)d_in[1];
    const float* w_out   = (const float*)d_in[2];
    const float* w_B     = (const float*)d_in[3];
    const float* w_C     = (const float*)d_in[4];
    const float* w_D1    = (const float*)d_in[5];
    const float* w_D2    = (const float*)d_in[6];
    const float* conv_w  = (const float*)d_in[7];
    const float* conv_b  = (const float*)d_in[8];
    const float* A_param = (const float*)d_in[9];
    const float* D_param = (const float*)d_in[10];
    float* out = (float*)d_out;

    float *ab_p, *a_p, *Bm_p, *Cm_p, *t_p, *delta_p, *y_p;
    cudaGetSymbolAddress((void**)&ab_p,    g_ab);
    cudaGetSymbolAddress((void**)&a_p,     g_a);
    cudaGetSymbolAddress((void**)&Bm_p,    g_Bm);
    cudaGetSymbolAddress((void**)&Cm_p,    g_Cm);
    cudaGetSymbolAddress((void**)&t_p,     g_t);
    cudaGetSymbolAddress((void**)&delta_p, g_delta);
    cudaGetSymbolAddress((void**)&y_p,     g_y);

    // 1) in_proj: ab = seq @ w_in^T   (2048 x 4096, K=1024)
    {
        dim3 grid(M_ROWS/128, (2*D_MODEL)/128, 1);
        sgemm_nt<128,128,16,8,8,0><<<grid, 256>>>(M_ROWS, 2*D_MODEL, D_IN,
                                                  seq, w_in, ab_p, nullptr, D_IN);
    }

    // 2) depthwise conv + bias + silu -> a
    {
        int n = B_SZ * L_SEQ * D_MODEL;
        conv_silu_kernel<<<(n + 255)/256, 256>>>(ab_p, conv_w, conv_b, a_p);
    }

    // zero split-K accumulators
    cudaMemsetAsync(Bm_p, 0, (size_t)M_ROWS * D_STATE * sizeof(float));
    cudaMemsetAsync(Cm_p, 0, (size_t)M_ROWS * D_STATE * sizeof(float));
    cudaMemsetAsync(t_p,  0, (size_t)M_ROWS * D_DISCR * sizeof(float));

    // 3) Bm = a @ w_B^T   (2048 x 16, K=2048), split-K=8
    {
        dim3 grid(M_ROWS/64, 1, 8);
        sgemm_nt<64,16,32,4,2,0><<<grid, 128>>>(M_ROWS, D_STATE, D_MODEL,
                                                a_p, w_B, Bm_p, nullptr, D_MODEL/8);
    }
    // 4) Cm = a @ w_C^T
    {
        dim3 grid(M_ROWS/64, 1, 8);
        sgemm_nt<64,16,32,4,2,0><<<grid, 128>>>(M_ROWS, D_STATE, D_MODEL,
                                                a_p, w_C, Cm_p, nullptr, D_MODEL/8);
    }
    // 5) t = a @ w_D1^T   (2048 x 128, K=2048), split-K=8
    {
        dim3 grid(M_ROWS/128, D_DISCR/128, 8);
        sgemm_nt<128,128,16,8,8,0><<<grid, 256>>>(M_ROWS, D_DISCR, D_MODEL,
                                                  a_p, w_D1, t_p, nullptr, D_MODEL/8);
    }
    // 6) delta = softplus(D_param + t @ w_D2^T)   (2048 x 2048, K=128)
    {
        dim3 grid(M_ROWS/128, D_MODEL/128, 1);
        sgemm_nt<128,128,16,8,8,1><<<grid, 256>>>(M_ROWS, D_MODEL, D_DISCR,
                                                  t_p, w_D2, delta_p, D_param, D_DISCR);
    }
    // 7) fused SSM scan + gating -> y
    {
        scan_kernel<<<(B_SZ*D_MODEL)/256, 256>>>(delta_p, a_p, ab_p, Bm_p, Cm_p,
                                                 A_param, D_param, y_p);
    }
    // 8) out = y @ w_out^T  (2048 x 1024, K=2048) -> d_out
    {
        dim3 grid(M_ROWS/128, D_IN/128, 1);
        sgemm_nt<128,128,16,8,8,0><<<grid, 256>>>(M_ROWS, D_IN, D_MODEL,
                                                  y_p, w_out, out, nullptr, D_MODEL);
    }
}

// round 4
// speedup vs baseline: 1.5379x; 1.5379x over previous
#include <cuda_runtime.h>
#include <cuda_bf16.h>
#include <cstdint>
#include <math.h>

// Problem constants
#define B_SZ 2
#define L_SEQ 1024
#define D_IN 1024
#define D_MODEL 2048
#define D_STATE 16
#define D_DISCR 128
#define KER 4
#define M_ROWS (B_SZ * L_SEQ)          // 2048

// ---------------- scratch (device globals; no allocation) ----------------
__device__ float g_ab[(size_t)M_ROWS * 2 * D_MODEL];   // in_proj out [2048,4096]
__device__ float g_a[(size_t)M_ROWS * D_MODEL];        // post conv+silu
__device__ float g_Bm[(size_t)M_ROWS * D_STATE];
__device__ float g_Cm[(size_t)M_ROWS * D_STATE];
__device__ float g_t[(size_t)M_ROWS * D_DISCR];        // a @ w_D1^T
__device__ float g_delta[(size_t)M_ROWS * D_MODEL];
__device__ float g_y[(size_t)M_ROWS * D_MODEL];        // pre out-proj

// ================= helpers =================
__device__ __forceinline__ uint32_t smem_u32(const void* p) {
    uint32_t a;
    asm("{ .reg .u64 t; cvta.to.shared.u64 t, %1; cvt.u32.u64 %0, t; }" : "=r"(a) : "l"(p));
    return a;
}
__device__ __forceinline__ void ldm4(uint32_t* r, uint32_t addr) {
    asm volatile("ldmatrix.sync.aligned.m8n8.x4.shared.b16 {%0,%1,%2,%3}, [%4];"
                 : "=r"(r[0]), "=r"(r[1]), "=r"(r[2]), "=r"(r[3]) : "r"(addr));
}
__device__ __forceinline__ void mma16816(float* c, const uint32_t* a, const uint32_t* b) {
    asm volatile("mma.sync.aligned.m16n8k16.row.col.f32.bf16.bf16.f32 "
                 "{%0,%1,%2,%3}, {%4,%5,%6,%7}, {%8,%9}, {%0,%1,%2,%3};"
                 : "+f"(c[0]), "+f"(c[1]), "+f"(c[2]), "+f"(c[3])
                 : "r"(a[0]), "r"(a[1]), "r"(a[2]), "r"(a[3]), "r"(b[0]), "r"(b[1]));
}
__device__ __forceinline__ void split4(float4 v, uint2& hi, uint2& lo) {
    float f[4] = {v.x, v.y, v.z, v.w};
    union { uint2 u; __nv_bfloat16 h[4]; } H, L;
#pragma unroll
    for (int i = 0; i < 4; i++) {
        __nv_bfloat16 b = __float2bfloat16(f[i]);
        H.h[i] = b;
        L.h[i] = __float2bfloat16(f[i] - __bfloat162float(b));
    }
    hi = H.u; lo = L.u;
}
// SW128-style swizzle for 128B rows: XOR 16B-group index with (row & 7)
__device__ __forceinline__ uint32_t swz(int r, int byteCol) {
    uint32_t off = (uint32_t)(r * 128 + byteCol);
    return off ^ (((uint32_t)r & 7u) << 4);
}

// ================= HMMA bf16-split NT GEMM =================
// C[m,n] = sum_k A[m,k] * W[n,k]; fp32 in/out via hi/lo bf16 split (3 MMAs).
// Block 128x128, BK=32, 256 threads (8 warps, 2x4), warp tile 64x32.
// SMEM row layout (128B): bytes [0,64) = hi (32 bf16), [64,128) = lo.
// EPI: 0 plain store, 1 softplus(bias[n]+v), 2 atomicAdd (split-K).
#define GSTAGE 32768                // As 16KB + Bs 16KB per stage
#define GSMEM  (2 * GSTAGE)        // 64 KB

template<int EPI>
__global__ __launch_bounds__(256, 1)
void mma_gemm(int M, int N, int K,
              const float* __restrict__ A,
              const float* __restrict__ W,
              float* __restrict__ C,
              const float* __restrict__ bias,
              int kPerSplit)
{
    extern __shared__ char smem[];
    const uint32_t sb = smem_u32(smem);
    const int tid = threadIdx.x;
    const int wid = tid >> 5, lane = tid & 31;
    const int wm = wid & 1, wn = wid >> 1;          // 2 x 4 warp grid
    const int row0 = blockIdx.x * 128;
    const int col0 = blockIdx.y * 128;
    const int k0 = blockIdx.z * kPerSplit;
    const int nCh = kPerSplit / 32;

    float acc[4][4][4];
#pragma unroll
    for (int i = 0; i < 4; i++)
#pragma unroll
        for (int j = 0; j < 4; j++)
#pragma unroll
            for (int q = 0; q < 4; q++) acc[i][j][q] = 0.f;

    const int cg = tid & 7;          // 8 groups of 4 fp32 across k
    const int rq = tid >> 3;         // 32 base rows

    for (int j = 0; j < nCh; j++) {
        const int st = j & 1;
        char* stA = smem + st * GSTAGE;
        char* stB = stA + 16384;
        const uint32_t sA = sb + st * GSTAGE;
        const uint32_t sB = sA + 16384;
        const int kt = k0 + j * 32;

        // ---- load + split A (128 x 32 fp32) ----
#pragma unroll
        for (int i = 0; i < 4; i++) {
            int r = rq + 32 * i;
            float4 v = *(const float4*)(A + (size_t)(row0 + r) * K + kt + cg * 4);
            uint2 hi, lo; split4(v, hi, lo);
            uint32_t sw = swz(r, cg * 8);
            *(uint2*)(stA + sw)        = hi;
            *(uint2*)(stA + (sw ^ 64)) = lo;
        }
        // ---- load + split B (128 x 32 fp32) ----
#pragma unroll
        for (int i = 0; i < 4; i++) {
            int r = rq + 32 * i;
            float4 v = *(const float4*)(W + (size_t)(col0 + r) * K + kt + cg * 4);
            uint2 hi, lo; split4(v, hi, lo);
            uint32_t sw = swz(r, cg * 8);
            *(uint2*)(stB + sw)        = hi;
            *(uint2*)(stB + (sw ^ 64)) = lo;
        }
        __syncthreads();

        // ---- compute: 2 k16 steps ----
#pragma unroll
        for (int s = 0; s < 2; s++) {
            uint32_t ah[4][4], al[4][4], bh[2][4], bl[2][4];
            // A fragments (m16k16): lanes 0-15 rows, 16-31 second k-group
            const int ra_l = (lane & 15);
            const int ga_l = (lane >> 4) * 16;
#pragma unroll
            for (int mi = 0; mi < 4; mi++) {
                int r = wm * 64 + mi * 16 + ra_l;
                ldm4(ah[mi], sA + swz(r, s * 32 + ga_l));        // hi
                ldm4(al[mi], sA + swz(r, 64 + s * 32 + ga_l));   // lo
            }
            // B fragments (two n8k16 per x4)
            const int rb_l = ((lane >> 4) & 1) * 8 + (lane & 7);
            const int gb_l = ((lane >> 3) & 1) * 16;
#pragma unroll
            for (int p = 0; p < 2; p++) {
                int r = wn * 32 + p * 16 + rb_l;
                ldm4(bh[p], sB + swz(r, s * 32 + gb_l));
                ldm4(bl[p], sB + swz(r, 64 + s * 32 + gb_l));
            }
#pragma unroll
            for (int mi = 0; mi < 4; mi++) {
#pragma unroll
                for (int ni = 0; ni < 4; ni++) {
                    const uint32_t* Bh = &bh[ni >> 1][(ni & 1) * 2];
                    const uint32_t* Bl = &bl[ni >> 1][(ni & 1) * 2];
                    mma16816(acc[mi][ni], ah[mi], Bh);
                    mma16816(acc[mi][ni], ah[mi], Bl);
                    mma16816(acc[mi][ni], al[mi], Bh);
                }
            }
        }
        __syncthreads();
    }

    // ---- epilogue ----
    const int er = (lane >> 2);
    const int ec = (lane & 3) * 2;
#pragma unroll
    for (int mi = 0; mi < 4; mi++) {
#pragma unroll
        for (int ni = 0; ni < 4; ni++) {
            int r = row0 + wm * 64 + mi * 16 + er;
            int c = col0 + wn * 32 + ni * 8 + ec;
            float v0 = acc[mi][ni][0], v1 = acc[mi][ni][1];
            float v2 = acc[mi][ni][2], v3 = acc[mi][ni][3];
            if (EPI == 1) {
                float b0 = bias[c], b1 = bias[c + 1];
                float x;
                x = b0 + v0; v0 = (x > 20.f) ? x : log1pf(expf(x));
                x = b1 + v1; v1 = (x > 20.f) ? x : log1pf(expf(x));
                x = b0 + v2; v2 = (x > 20.f) ? x : log1pf(expf(x));
                x = b1 + v3; v3 = (x > 20.f) ? x : log1pf(expf(x));
            }
            if (EPI == 2) {
                atomicAdd(C + (size_t)r * N + c,           v0);
                atomicAdd(C + (size_t)r * N + c + 1,       v1);
                atomicAdd(C + (size_t)(r + 8) * N + c,     v2);
                atomicAdd(C + (size_t)(r + 8) * N + c + 1, v3);
            } else {
                float2 p0 = {v0, v1}, p1 = {v2, v3};
                *(float2*)(C + (size_t)r * N + c)       = p0;
                *(float2*)(C + (size_t)(r + 8) * N + c) = p1;
            }
        }
    }
}

// ================= SIMT split-K GEMM for B/C (N=16), fused launch ==========
__global__ __launch_bounds__(128)
void sgemm_bc(const float* __restrict__ A,
              const float* __restrict__ wB,
              const float* __restrict__ wC,
              float* __restrict__ Bm,
              float* __restrict__ Cm,
              int kPerSplit)
{
    constexpr int BM = 64, BN = 16, BK = 32, TM = 4, TN = 2;
    const float* W = (blockIdx.y == 0) ? wB : wC;
    float* C = (blockIdx.y == 0) ? Bm : Cm;
    const int M = M_ROWS, N = D_STATE, K = D_MODEL;

    __shared__ float As[BK][BM];
    __shared__ float Ws[BK][BN];

    const int tid  = threadIdx.x;
    const int row0 = blockIdx.x * BM;
    const int k0   = blockIdx.z * kPerSplit;
    const int kEnd = k0 + kPerSplit;

    const int aCol = tid % (BK / 4);
    const int aRow = tid / (BK / 4);
    const int tRow = (tid / (BN / TN)) * TM;
    const int tCol = (tid % (BN / TN)) * TN;

    float acc[TM][TN];
#pragma unroll
    for (int i = 0; i < TM; i++)
#pragma unroll
        for (int j = 0; j < TN; j++) acc[i][j] = 0.f;

    for (int kt = k0; kt < kEnd; kt += BK) {
#pragma unroll
        for (int i = 0; i < BM; i += 16) {
            float4 v = *(const float4*)(A + (size_t)(row0 + aRow + i) * K + kt + aCol * 4);
            As[aCol*4 + 0][aRow + i] = v.x;
            As[aCol*4 + 1][aRow + i] = v.y;
            As[aCol*4 + 2][aRow + i] = v.z;
            As[aCol*4 + 3][aRow + i] = v.w;
        }
        {
            float4 v = *(const float4*)(W + (size_t)aRow * K + kt + aCol * 4);
            Ws[aCol*4 + 0][aRow] = v.x;
            Ws[aCol*4 + 1][aRow] = v.y;
            Ws[aCol*4 + 2][aRow] = v.z;
            Ws[aCol*4 + 3][aRow] = v.w;
        }
        __syncthreads();
#pragma unroll
        for (int kk = 0; kk < BK; kk++) {
            float rm[TM], rn[TN];
#pragma unroll
            for (int i = 0; i < TM; i++) rm[i] = As[kk][tRow + i];
#pragma unroll
            for (int j = 0; j < TN; j++) rn[j] = Ws[kk][tCol + j];
#pragma unroll
            for (int i = 0; i < TM; i++)
#pragma unroll
                for (int j = 0; j < TN; j++) acc[i][j] = fmaf(rm[i], rn[j], acc[i][j]);
        }
        __syncthreads();
    }
#pragma unroll
    for (int i = 0; i < TM; i++)
#pragma unroll
        for (int j = 0; j < TN; j++)
            atomicAdd(C + (size_t)(row0 + tRow + i) * N + tCol + j, acc[i][j]);
}

// ---------------- depthwise causal conv (ker=4) + bias + SiLU ----------------
__global__ void conv_silu_kernel(const float* __restrict__ ab,
                                 const float* __restrict__ cw,
                                 const float* __restrict__ cb,
                                 float* __restrict__ a_out)
{
    int idx = blockIdx.x * blockDim.x + threadIdx.x;
    if (idx >= B_SZ * L_SEQ * D_MODEL) return;
    int d = idx & (D_MODEL - 1);
    int l = (idx >> 11) & (L_SEQ - 1);
    int b = idx >> 21;

    float w0 = cw[d*4+0], w1 = cw[d*4+1], w2 = cw[d*4+2], w3 = cw[d*4+3];
    const size_t rowBase = ((size_t)b * L_SEQ) * (2*D_MODEL);
    float s = cb[d];
    if (l >= 3) s += w0 * ab[rowBase + (size_t)(l-3)*(2*D_MODEL) + d];
    if (l >= 2) s += w1 * ab[rowBase + (size_t)(l-2)*(2*D_MODEL) + d];
    if (l >= 1) s += w2 * ab[rowBase + (size_t)(l-1)*(2*D_MODEL) + d];
    s += w3 * ab[rowBase + (size_t)l*(2*D_MODEL) + d];
    a_out[idx] = s / (1.f + expf(-s));
}

// ---------------- fused SSM scan + output gating ----------------
__global__ __launch_bounds__(128)
void scan_kernel(const float* __restrict__ delta,
                 const float* __restrict__ a,
                 const float* __restrict__ ab,   // gate at column offset D_MODEL
                 const float* __restrict__ Bm,
                 const float* __restrict__ Cm,
                 const float* __restrict__ A_param,
                 const float* __restrict__ D_param,
                 float* __restrict__ y)
{
    int gid = blockIdx.x * blockDim.x + threadIdx.x;     // over B*DM = 4096
    if (gid >= B_SZ * D_MODEL) return;
    int b = gid >> 11;
    int d = gid & (D_MODEL - 1);

    float expA[D_STATE];
#pragma unroll
    for (int s = 0; s < D_STATE; s++) expA[s] = expf(-A_param[(size_t)d * D_STATE + s]);
    const float Dp = D_param[d];

    float h[D_STATE];
#pragma unroll
    for (int s = 0; s < D_STATE; s++) h[s] = 0.f;

    const size_t chanBase = (size_t)b * L_SEQ;
    for (int l = 0; l < L_SEQ; l++) {
        const size_t row = chanBase + l;
        const size_t idx = row * D_MODEL + d;
        float dlt = delta[idx];
        float av  = a[idx];
        float gt  = ab[row * (2*D_MODEL) + D_MODEL + d];

        const float4* Bp = (const float4*)(Bm + row * D_STATE);
        const float4* Cp = (const float4*)(Cm + row * D_STATE);
        float4 B0 = Bp[0], B1 = Bp[1], B2 = Bp[2], B3 = Bp[3];
        float4 C0 = Cp[0], C1 = Cp[1], C2 = Cp[2], C3 = Cp[3];
        float Bv[16] = {B0.x,B0.y,B0.z,B0.w, B1.x,B1.y,B1.z,B1.w,
                        B2.x,B2.y,B2.z,B2.w, B3.x,B3.y,B3.z,B3.w};
        float Cv[16] = {C0.x,C0.y,C0.z,C0.w, C1.x,C1.y,C1.z,C1.w,
                        C2.x,C2.y,C2.z,C2.w, C3.x,C3.y,C3.z,C3.w};

        float xc = dlt * av;
        float acc0 = 0.f, acc1 = 0.f;
#pragma unroll
        for (int s = 0; s < D_STATE; s += 2) {
            h[s]   = fmaf(expA[s]   * dlt, h[s],   Bv[s]   * xc);
            h[s+1] = fmaf(expA[s+1] * dlt, h[s+1], Bv[s+1] * xc);
            acc0   = fmaf(h[s],   Cv[s],   acc0);
            acc1   = fmaf(h[s+1], Cv[s+1], acc1);
        }
        float silu_g = gt / (1.f + expf(-gt));
        y[idx] = (acc0 + acc1 + Dp * av) * silu_g;
    }
}

// ---------------- launch ----------------
extern "C" void kernel_launch(void* const* d_in, const int* in_sizes, int n_in,
                              void* d_out, int out_size)
{
    const float* seq     = (const float*)d_in[0];
    const float* w_in    = (const float*)d_in[1];
    const float* w_out   = (const float*)d_in[2];
    const float* w_B     = (const float*)d_in[3];
    const float* w_C     = (const float*)d_in[4];
    const float* w_D1    = (const float*)d_in[5];
    const float* w_D2    = (const float*)d_in[6];
    const float* conv_w  = (const float*)d_in[7];
    const float* conv_b  = (const float*)d_in[8];
    const float* A_param = (const float*)d_in[9];
    const float* D_param = (const float*)d_in[10];
    float* out = (float*)d_out;

    float *ab_p, *a_p, *Bm_p, *Cm_p, *t_p, *delta_p, *y_p;
    cudaGetSymbolAddress((void**)&ab_p,    g_ab);
    cudaGetSymbolAddress((void**)&a_p,     g_a);
    cudaGetSymbolAddress((void**)&Bm_p,    g_Bm);
    cudaGetSymbolAddress((void**)&Cm_p,    g_Cm);
    cudaGetSymbolAddress((void**)&t_p,     g_t);
    cudaGetSymbolAddress((void**)&delta_p, g_delta);
    cudaGetSymbolAddress((void**)&y_p,     g_y);

    cudaFuncSetAttribute(mma_gemm<0>, cudaFuncAttributeMaxDynamicSharedMemorySize, GSMEM);
    cudaFuncSetAttribute(mma_gemm<1>, cudaFuncAttributeMaxDynamicSharedMemorySize, GSMEM);
    cudaFuncSetAttribute(mma_gemm<2>, cudaFuncAttributeMaxDynamicSharedMemorySize, GSMEM);

    // 1) in_proj: ab = seq @ w_in^T   (2048 x 4096, K=1024)
    {
        dim3 grid(M_ROWS/128, (2*D_MODEL)/128, 1);
        mma_gemm<0><<<grid, 256, GSMEM>>>(M_ROWS, 2*D_MODEL, D_IN,
                                          seq, w_in, ab_p, nullptr, D_IN);
    }
    // 2) depthwise conv + bias + silu -> a
    {
        int n = B_SZ * L_SEQ * D_MODEL;
        conv_silu_kernel<<<(n + 255)/256, 256>>>(ab_p, conv_w, conv_b, a_p);
    }
    // zero split-K accumulators
    cudaMemsetAsync(Bm_p, 0, (size_t)M_ROWS * D_STATE * sizeof(float));
    cudaMemsetAsync(Cm_p, 0, (size_t)M_ROWS * D_STATE * sizeof(float));
    cudaMemsetAsync(t_p,  0, (size_t)M_ROWS * D_DISCR * sizeof(float));

    // 3+4) Bm/Cm = a @ {w_B,w_C}^T   (2048 x 16, K=2048), fused, split-K=16
    {
        dim3 grid(M_ROWS/64, 2, 16);
        sgemm_bc<<<grid, 128>>>(a_p, w_B, w_C, Bm_p, Cm_p, D_MODEL/16);
    }
    // 5) t = a @ w_D1^T   (2048 x 128, K=2048), split-K=4
    {
        dim3 grid(M_ROWS/128, D_DISCR/128, 4);
        mma_gemm<2><<<grid, 256, GSMEM>>>(M_ROWS, D_DISCR, D_MODEL,
                                          a_p, w_D1, t_p, nullptr, D_MODEL/4);
    }
    // 6) delta = softplus(D_param + t @ w_D2^T)   (2048 x 2048, K=128)
    {
        dim3 grid(M_ROWS/128, D_MODEL/128, 1);
        mma_gemm<1><<<grid, 256, GSMEM>>>(M_ROWS, D_MODEL, D_DISCR,
                                          t_p, w_D2, delta_p, D_param, D_DISCR);
    }
    // 7) fused SSM scan + gating -> y
    {
        scan_kernel<<<(B_SZ*D_MODEL)/128, 128>>>(delta_p, a_p, ab_p, Bm_p, Cm_p,
                                                 A_param, D_param, y_p);
    }
    // 8) out = y @ w_out^T  (2048 x 1024, K=2048) -> d_out
    {
        dim3 grid(M_ROWS/128, D_IN/128, 1);
        mma_gemm<0><<<grid, 256, GSMEM>>>(M_ROWS, D_IN, D_MODEL,
                                          y_p, w_out, out, nullptr, D_MODEL);
    }
}

// round 5
// speedup vs baseline: 1.5650x; 1.0176x over previous
#include <cuda_runtime.h>
#include <cuda_bf16.h>
#include <cstdint>
#include <math.h>

// Problem constants
#define B_SZ 2
#define L_SEQ 1024
#define D_IN 1024
#define D_MODEL 2048
#define D_STATE 16
#define D_DISCR 128
#define KER 4
#define M_ROWS (B_SZ * L_SEQ)          // 2048

// ---------------- scratch (device globals; no allocation) ----------------
__device__ float g_ab[(size_t)M_ROWS * 2 * D_MODEL];   // in_proj out [2048,4096]
__device__ float g_a[(size_t)M_ROWS * D_MODEL];        // post conv+silu (fp32, for scan + B/C)
__device__ float g_Bm[(size_t)M_ROWS * D_STATE];
__device__ float g_Cm[(size_t)M_ROWS * D_STATE];
__device__ float g_t[(size_t)M_ROWS * D_DISCR];        // a @ w_D1^T (fp32 split-K acc)
__device__ float g_delta[(size_t)M_ROWS * D_MODEL];
// converted hi/lo bf16 operand buffers: layout [R][2K] bf16 (hi cols 0..K-1, lo cols K..2K-1)
__device__ __nv_bfloat16 g_seq_c [(size_t)M_ROWS * 2 * D_IN];
__device__ __nv_bfloat16 g_win_c [(size_t)(2*D_MODEL) * 2 * D_IN];
__device__ __nv_bfloat16 g_a_c   [(size_t)M_ROWS * 2 * D_MODEL];
__device__ __nv_bfloat16 g_wd1_c [(size_t)D_DISCR * 2 * D_MODEL];
__device__ __nv_bfloat16 g_wd2_c [(size_t)D_MODEL * 2 * D_DISCR];
__device__ __nv_bfloat16 g_t_c   [(size_t)M_ROWS * 2 * D_DISCR];
__device__ __nv_bfloat16 g_wout_c[(size_t)D_IN * 2 * D_MODEL];
__device__ __nv_bfloat16 g_y_c   [(size_t)M_ROWS * 2 * D_MODEL];

// ================= helpers =================
__device__ __forceinline__ uint32_t smem_u32(const void* p) {
    uint32_t a;
    asm("{ .reg .u64 t; cvta.to.shared.u64 t, %1; cvt.u32.u64 %0, t; }" : "=r"(a) : "l"(p));
    return a;
}
__device__ __forceinline__ void ldm4(uint32_t* r, uint32_t addr) {
    asm volatile("ldmatrix.sync.aligned.m8n8.x4.shared.b16 {%0,%1,%2,%3}, [%4];"
                 : "=r"(r[0]), "=r"(r[1]), "=r"(r[2]), "=r"(r[3]) : "r"(addr));
}
__device__ __forceinline__ void mma16816(float* c, const uint32_t* a, const uint32_t* b) {
    asm volatile("mma.sync.aligned.m16n8k16.row.col.f32.bf16.bf16.f32 "
                 "{%0,%1,%2,%3}, {%4,%5,%6,%7}, {%8,%9}, {%0,%1,%2,%3};"
                 : "+f"(c[0]), "+f"(c[1]), "+f"(c[2]), "+f"(c[3])
                 : "r"(a[0]), "r"(a[1]), "r"(a[2]), "r"(a[3]), "r"(b[0]), "r"(b[1]));
}
__device__ __forceinline__ void cp16(uint32_t dst, const void* src) {
    asm volatile("cp.async.cg.shared.global [%0], [%1], 16;" :: "r"(dst), "l"(src));
}
__device__ __forceinline__ void cp_commit() {
    asm volatile("cp.async.commit_group;" ::: "memory");
}
template<int N>
__device__ __forceinline__ void cp_wait() {
    asm volatile("cp.async.wait_group %0;" :: "n"(N) : "memory");
}
__device__ __forceinline__ void hilo(float f, __nv_bfloat16& h, __nv_bfloat16& l) {
    h = __float2bfloat16(f);
    l = __float2bfloat16(f - __bfloat162float(h));
}
// swizzle for 128B smem rows: XOR 16B-group index with (row & 7)
__device__ __forceinline__ uint32_t swz(int r, int byteCol) {
    uint32_t off = (uint32_t)(r * 128 + byteCol);
    return off ^ (((uint32_t)r & 7u) << 4);
}

// ================= convert fp32 [R][K] -> packed hi/lo bf16 [R][2K] ==========
__global__ void convert_hilo(const float* __restrict__ X, __nv_bfloat16* __restrict__ Y,
                             int R, int K)
{
    int idx = blockIdx.x * blockDim.x + threadIdx.x;      // over R*K/4
    if (idx >= (R * K) >> 2) return;
    int perRow = K >> 2;
    int r = idx / perRow;
    int k = (idx - r * perRow) << 2;
    float4 v = *(const float4*)(X + (size_t)r * K + k);
    union { uint2 u; __nv_bfloat16 h[4]; } H, L;
    hilo(v.x, H.h[0], L.h[0]); hilo(v.y, H.h[1], L.h[1]);
    hilo(v.z, H.h[2], L.h[2]); hilo(v.w, H.h[3], L.h[3]);
    __nv_bfloat16* row = Y + (size_t)r * 2 * K;
    *(uint2*)(row + k)     = H.u;
    *(uint2*)(row + K + k) = L.u;
}

// ================= pipelined HMMA bf16-split NT GEMM =================
// C[m,n] = sum_k A[m,k]*W[n,k]; operands are packed hi/lo bf16 [R][2K].
// Block 128x128, BK=32, 256 thr (8 warps 2x4), warp tile 64x32, 4-stage cp.async.
// SMEM stage: A 128 rows x 128B (hi 64B | lo 64B, swizzled) + B same = 32KB.
// EPI: 0 plain store, 1 softplus(bias[n]+v), 2 atomicAdd (split-K).
#define STG 32768
#define NSTG 4
#define GSMEM (NSTG * STG)   // 128 KB

template<int EPI>
__global__ __launch_bounds__(256, 1)
void mma_gemm(int M, int N, int K,
              const __nv_bfloat16* __restrict__ A,
              const __nv_bfloat16* __restrict__ W,
              float* __restrict__ C,
              const float* __restrict__ bias,
              int kPerSplit)
{
    extern __shared__ char smem[];
    const uint32_t sb = smem_u32(smem);
    const int tid = threadIdx.x;
    const int wid = tid >> 5, lane = tid & 31;
    const int wm = wid & 1, wn = wid >> 1;          // 2 x 4 warp grid
    const int row0 = blockIdx.x * 128;
    const int col0 = blockIdx.y * 128;
    const int k0 = blockIdx.z * kPerSplit;
    const int nCh = kPerSplit / 32;

    const size_t rowBytesA = (size_t)2 * K * 2;     // bytes per row of packed operand
    const char* Ab = (const char*)A;
    const char* Wb = (const char*)W;

    // issue one stage's cp.async (A tile + B tile); 8 chunks of 16B per thread
    auto issue = [&](int j) {
        const int st = j & (NSTG - 1);
        const uint32_t stA = sb + st * STG;
        const uint32_t stB = stA + 16384;
        const int kt = k0 + j * 32;
#pragma unroll
        for (int i = 0; i < 4; i++) {
            int c = i * 256 + tid;          // 0..1023
            int r = c >> 3, g = c & 7;
            size_t srcOff = (size_t)(row0 + r) * rowBytesA +
                            ((g < 4) ? ((size_t)kt * 2 + g * 16)
                                     : ((size_t)K * 2 + (size_t)kt * 2 + (g - 4) * 16));
            cp16(stA + swz(r, g * 16), Ab + srcOff);
        }
#pragma unroll
        for (int i = 0; i < 4; i++) {
            int c = i * 256 + tid;
            int r = c >> 3, g = c & 7;
            size_t srcOff = (size_t)(col0 + r) * rowBytesA +
                            ((g < 4) ? ((size_t)kt * 2 + g * 16)
                                     : ((size_t)K * 2 + (size_t)kt * 2 + (g - 4) * 16));
            cp16(stB + swz(r, g * 16), Wb + srcOff);
        }
        cp_commit();
    };

    float acc[4][4][4];
#pragma unroll
    for (int i = 0; i < 4; i++)
#pragma unroll
        for (int j = 0; j < 4; j++)
#pragma unroll
            for (int q = 0; q < 4; q++) acc[i][j][q] = 0.f;

    // prologue: fill up to NSTG-1 stages
    const int pre = (nCh < NSTG - 1) ? nCh : (NSTG - 1);
    for (int j = 0; j < pre; j++) issue(j);

    const int ra_l = (lane & 15);
    const int ga_l = (lane >> 4) * 16;
    const int rb_l = ((lane >> 4) & 1) * 8 + (lane & 7);
    const int gb_l = ((lane >> 3) & 1) * 16;

    for (int j = 0; j < nCh; j++) {
        // ensure group j complete: pending-after-j = min(NSTG-2, nCh-1-j)
        int newer = nCh - 1 - j; if (newer > NSTG - 2) newer = NSTG - 2;
        if (newer == 2) cp_wait<2>(); else if (newer == 1) cp_wait<1>(); else cp_wait<0>();
        __syncthreads();

        if (j + NSTG - 1 < nCh) issue(j + NSTG - 1);

        const int st = j & (NSTG - 1);
        const uint32_t sA = sb + st * STG;
        const uint32_t sB = sA + 16384;

#pragma unroll
        for (int s = 0; s < 2; s++) {
            uint32_t ah[4][4], al[4][4], bh[2][4], bl[2][4];
#pragma unroll
            for (int mi = 0; mi < 4; mi++) {
                int r = wm * 64 + mi * 16 + ra_l;
                ldm4(ah[mi], sA + swz(r, s * 32 + ga_l));        // hi
                ldm4(al[mi], sA + swz(r, 64 + s * 32 + ga_l));   // lo
            }
#pragma unroll
            for (int p = 0; p < 2; p++) {
                int r = wn * 32 + p * 16 + rb_l;
                ldm4(bh[p], sB + swz(r, s * 32 + gb_l));
                ldm4(bl[p], sB + swz(r, 64 + s * 32 + gb_l));
            }
#pragma unroll
            for (int mi = 0; mi < 4; mi++) {
#pragma unroll
                for (int ni = 0; ni < 4; ni++) {
                    const uint32_t* Bh = &bh[ni >> 1][(ni & 1) * 2];
                    const uint32_t* Bl = &bl[ni >> 1][(ni & 1) * 2];
                    mma16816(acc[mi][ni], ah[mi], Bh);
                    mma16816(acc[mi][ni], ah[mi], Bl);
                    mma16816(acc[mi][ni], al[mi], Bh);
                }
            }
        }
        __syncthreads();
    }

    // ---- epilogue ----
    const int er = (lane >> 2);
    const int ec = (lane & 3) * 2;
#pragma unroll
    for (int mi = 0; mi < 4; mi++) {
#pragma unroll
        for (int ni = 0; ni < 4; ni++) {
            int r = row0 + wm * 64 + mi * 16 + er;
            int c = col0 + wn * 32 + ni * 8 + ec;
            float v0 = acc[mi][ni][0], v1 = acc[mi][ni][1];
            float v2 = acc[mi][ni][2], v3 = acc[mi][ni][3];
            if (EPI == 1) {
                float b0 = bias[c], b1 = bias[c + 1];
                float x;
                x = b0 + v0; v0 = (x > 20.f) ? x : log1pf(expf(x));
                x = b1 + v1; v1 = (x > 20.f) ? x : log1pf(expf(x));
                x = b0 + v2; v2 = (x > 20.f) ? x : log1pf(expf(x));
                x = b1 + v3; v3 = (x > 20.f) ? x : log1pf(expf(x));
            }
            if (EPI == 2) {
                atomicAdd(C + (size_t)r * N + c,           v0);
                atomicAdd(C + (size_t)r * N + c + 1,       v1);
                atomicAdd(C + (size_t)(r + 8) * N + c,     v2);
                atomicAdd(C + (size_t)(r + 8) * N + c + 1, v3);
            } else {
                float2 p0 = {v0, v1}, p1 = {v2, v3};
                *(float2*)(C + (size_t)r * N + c)       = p0;
                *(float2*)(C + (size_t)(r + 8) * N + c) = p1;
            }
        }
    }
}

// ================= SIMT split-K GEMM for B/C (N=16), fused launch ==========
__global__ __launch_bounds__(128)
void sgemm_bc(const float* __restrict__ A,
              const float* __restrict__ wB,
              const float* __restrict__ wC,
              float* __restrict__ Bm,
              float* __restrict__ Cm,
              int kPerSplit)
{
    constexpr int BM = 64, BN = 16, BK = 32, TM = 4, TN = 2;
    const float* W = (blockIdx.y == 0) ? wB : wC;
    float* C = (blockIdx.y == 0) ? Bm : Cm;
    const int N = D_STATE, K = D_MODEL;

    __shared__ float As[BK][BM];
    __shared__ float Ws[BK][BN];

    const int tid  = threadIdx.x;
    const int row0 = blockIdx.x * BM;
    const int k0   = blockIdx.z * kPerSplit;
    const int kEnd = k0 + kPerSplit;

    const int aCol = tid % (BK / 4);
    const int aRow = tid / (BK / 4);
    const int tRow = (tid / (BN / TN)) * TM;
    const int tCol = (tid % (BN / TN)) * TN;

    float acc[TM][TN];
#pragma unroll
    for (int i = 0; i < TM; i++)
#pragma unroll
        for (int j = 0; j < TN; j++) acc[i][j] = 0.f;

    for (int kt = k0; kt < kEnd; kt += BK) {
#pragma unroll
        for (int i = 0; i < BM; i += 16) {
            float4 v = *(const float4*)(A + (size_t)(row0 + aRow + i) * K + kt + aCol * 4);
            As[aCol*4 + 0][aRow + i] = v.x;
            As[aCol*4 + 1][aRow + i] = v.y;
            As[aCol*4 + 2][aRow + i] = v.z;
            As[aCol*4 + 3][aRow + i] = v.w;
        }
        {
            float4 v = *(const float4*)(W + (size_t)aRow * K + kt + aCol * 4);
            Ws[aCol*4 + 0][aRow] = v.x;
            Ws[aCol*4 + 1][aRow] = v.y;
            Ws[aCol*4 + 2][aRow] = v.z;
            Ws[aCol*4 + 3][aRow] = v.w;
        }
        __syncthreads();
#pragma unroll
        for (int kk = 0; kk < BK; kk++) {
            float rm[TM], rn[TN];
#pragma unroll
            for (int i = 0; i < TM; i++) rm[i] = As[kk][tRow + i];
#pragma unroll
            for (int j = 0; j < TN; j++) rn[j] = Ws[kk][tCol + j];
#pragma unroll
            for (int i = 0; i < TM; i++)
#pragma unroll
                for (int j = 0; j < TN; j++) acc[i][j] = fmaf(rm[i], rn[j], acc[i][j]);
        }
        __syncthreads();
    }
#pragma unroll
    for (int i = 0; i < TM; i++)
#pragma unroll
        for (int j = 0; j < TN; j++)
            atomicAdd(C + (size_t)(row0 + tRow + i) * N + tCol + j, acc[i][j]);
}

// ------ depthwise causal conv (ker=4) + bias + SiLU; writes a fp32 AND a_c ------
__global__ void conv_silu_kernel(const float* __restrict__ ab,
                                 const float* __restrict__ cw,
                                 const float* __restrict__ cb,
                                 float* __restrict__ a_out,
                                 __nv_bfloat16* __restrict__ a_c)
{
    int idx = blockIdx.x * blockDim.x + threadIdx.x;
    if (idx >= B_SZ * L_SEQ * D_MODEL) return;
    int d = idx & (D_MODEL - 1);
    int l = (idx >> 11) & (L_SEQ - 1);
    int b = idx >> 21;

    float w0 = cw[d*4+0], w1 = cw[d*4+1], w2 = cw[d*4+2], w3 = cw[d*4+3];
    const size_t rowBase = ((size_t)b * L_SEQ) * (2*D_MODEL);
    float s = cb[d];
    if (l >= 3) s += w0 * ab[rowBase + (size_t)(l-3)*(2*D_MODEL) + d];
    if (l >= 2) s += w1 * ab[rowBase + (size_t)(l-2)*(2*D_MODEL) + d];
    if (l >= 1) s += w2 * ab[rowBase + (size_t)(l-1)*(2*D_MODEL) + d];
    s += w3 * ab[rowBase + (size_t)l*(2*D_MODEL) + d];
    float v = s / (1.f + expf(-s));
    a_out[idx] = v;
    // packed hi/lo row
    __nv_bfloat16 h, lo; hilo(v, h, lo);
    size_t row = (size_t)(b * L_SEQ + l) * 2 * D_MODEL;
    a_c[row + d]           = h;
    a_c[row + D_MODEL + d] = lo;
}

// ---------------- fused SSM scan + output gating -> y_c (packed bf16) --------
__global__ __launch_bounds__(128)
void scan_kernel(const float* __restrict__ delta,
                 const float* __restrict__ a,
                 const float* __restrict__ ab,   // gate at column offset D_MODEL
                 const float* __restrict__ Bm,
                 const float* __restrict__ Cm,
                 const float* __restrict__ A_param,
                 const float* __restrict__ D_param,
                 __nv_bfloat16* __restrict__ y_c)
{
    int gid = blockIdx.x * blockDim.x + threadIdx.x;     // over B*DM = 4096
    if (gid >= B_SZ * D_MODEL) return;
    int b = gid >> 11;
    int d = gid & (D_MODEL - 1);

    float expA[D_STATE];
#pragma unroll
    for (int s = 0; s < D_STATE; s++) expA[s] = expf(-A_param[(size_t)d * D_STATE + s]);
    const float Dp = D_param[d];

    float h[D_STATE];
#pragma unroll
    for (int s = 0; s < D_STATE; s++) h[s] = 0.f;

    const size_t chanBase = (size_t)b * L_SEQ;
    for (int l = 0; l < L_SEQ; l++) {
        const size_t row = chanBase + l;
        const size_t idx = row * D_MODEL + d;
        float dlt = delta[idx];
        float av  = a[idx];
        float gt  = ab[row * (2*D_MODEL) + D_MODEL + d];

        const float4* Bp = (const float4*)(Bm + row * D_STATE);
        const float4* Cp = (const float4*)(Cm + row * D_STATE);
        float4 B0 = Bp[0], B1 = Bp[1], B2 = Bp[2], B3 = Bp[3];
        float4 C0 = Cp[0], C1 = Cp[1], C2 = Cp[2], C3 = Cp[3];
        float Bv[16] = {B0.x,B0.y,B0.z,B0.w, B1.x,B1.y,B1.z,B1.w,
                        B2.x,B2.y,B2.z,B2.w, B3.x,B3.y,B3.z,B3.w};
        float Cv[16] = {C0.x,C0.y,C0.z,C0.w, C1.x,C1.y,C1.z,C1.w,
                        C2.x,C2.y,C2.z,C2.w, C3.x,C3.y,C3.z,C3.w};

        float xc = dlt * av;
        float acc0 = 0.f, acc1 = 0.f;
#pragma unroll
        for (int s = 0; s < D_STATE; s += 2) {
            h[s]   = fmaf(expA[s]   * dlt, h[s],   Bv[s]   * xc);
            h[s+1] = fmaf(expA[s+1] * dlt, h[s+1], Bv[s+1] * xc);
            acc0   = fmaf(h[s],   Cv[s],   acc0);
            acc1   = fmaf(h[s+1], Cv[s+1], acc1);
        }
        float silu_g = gt / (1.f + expf(-gt));
        float yv = (acc0 + acc1 + Dp * av) * silu_g;
        __nv_bfloat16 hh, ll; hilo(yv, hh, ll);
        __nv_bfloat16* yrow = y_c + row * 2 * D_MODEL;
        yrow[d]           = hh;
        yrow[D_MODEL + d] = ll;
    }
}

// ---------------- launch ----------------
extern "C" void kernel_launch(void* const* d_in, const int* in_sizes, int n_in,
                              void* d_out, int out_size)
{
    const float* seq     = (const float*)d_in[0];
    const float* w_in    = (const float*)d_in[1];
    const float* w_out   = (const float*)d_in[2];
    const float* w_B     = (const float*)d_in[3];
    const float* w_C     = (const float*)d_in[4];
    const float* w_D1    = (const float*)d_in[5];
    const float* w_D2    = (const float*)d_in[6];
    const float* conv_w  = (const float*)d_in[7];
    const float* conv_b  = (const float*)d_in[8];
    const float* A_param = (const float*)d_in[9];
    const float* D_param = (const float*)d_in[10];
    float* out = (float*)d_out;

    float *ab_p, *a_p, *Bm_p, *Cm_p, *t_p, *delta_p;
    __nv_bfloat16 *seq_c, *win_c, *a_c, *wd1_c, *wd2_c, *t_c, *wout_c, *y_c;
    cudaGetSymbolAddress((void**)&ab_p,    g_ab);
    cudaGetSymbolAddress((void**)&a_p,     g_a);
    cudaGetSymbolAddress((void**)&Bm_p,    g_Bm);
    cudaGetSymbolAddress((void**)&Cm_p,    g_Cm);
    cudaGetSymbolAddress((void**)&t_p,     g_t);
    cudaGetSymbolAddress((void**)&delta_p, g_delta);
    cudaGetSymbolAddress((void**)&seq_c,   g_seq_c);
    cudaGetSymbolAddress((void**)&win_c,   g_win_c);
    cudaGetSymbolAddress((void**)&a_c,     g_a_c);
    cudaGetSymbolAddress((void**)&wd1_c,   g_wd1_c);
    cudaGetSymbolAddress((void**)&wd2_c,   g_wd2_c);
    cudaGetSymbolAddress((void**)&t_c,     g_t_c);
    cudaGetSymbolAddress((void**)&wout_c,  g_wout_c);
    cudaGetSymbolAddress((void**)&y_c,     g_y_c);

    cudaFuncSetAttribute(mma_gemm<0>, cudaFuncAttributeMaxDynamicSharedMemorySize, GSMEM);
    cudaFuncSetAttribute(mma_gemm<1>, cudaFuncAttributeMaxDynamicSharedMemorySize, GSMEM);
    cudaFuncSetAttribute(mma_gemm<2>, cudaFuncAttributeMaxDynamicSharedMemorySize, GSMEM);

    auto conv = [&](const float* X, __nv_bfloat16* Y, int R, int K) {
        int n = (R * K) >> 2;
        convert_hilo<<<(n + 255)/256, 256>>>(X, Y, R, K);
    };

    // 0) convert inputs / weights
    conv(seq,   seq_c,  M_ROWS,     D_IN);
    conv(w_in,  win_c,  2*D_MODEL,  D_IN);
    conv(w_D1,  wd1_c,  D_DISCR,    D_MODEL);
    conv(w_D2,  wd2_c,  D_MODEL,    D_DISCR);
    conv(w_out, wout_c, D_IN,       D_MODEL);

    // 1) in_proj: ab = seq @ w_in^T   (2048 x 4096, K=1024)
    {
        dim3 grid(M_ROWS/128, (2*D_MODEL)/128, 1);
        mma_gemm<0><<<grid, 256, GSMEM>>>(M_ROWS, 2*D_MODEL, D_IN,
                                          seq_c, win_c, ab_p, nullptr, D_IN);
    }
    // 2) depthwise conv + bias + silu -> a (fp32) + a_c (packed bf16)
    {
        int n = B_SZ * L_SEQ * D_MODEL;
        conv_silu_kernel<<<(n + 255)/256, 256>>>(ab_p, conv_w, conv_b, a_p, a_c);
    }
    // zero split-K accumulators
    cudaMemsetAsync(Bm_p, 0, (size_t)M_ROWS * D_STATE * sizeof(float));
    cudaMemsetAsync(Cm_p, 0, (size_t)M_ROWS * D_STATE * sizeof(float));
    cudaMemsetAsync(t_p,  0, (size_t)M_ROWS * D_DISCR * sizeof(float));

    // 3+4) Bm/Cm = a @ {w_B,w_C}^T   (2048 x 16, K=2048), fused, split-K=16
    {
        dim3 grid(M_ROWS/64, 2, 16);
        sgemm_bc<<<grid, 128>>>(a_p, w_B, w_C, Bm_p, Cm_p, D_MODEL/16);
    }
    // 5) t = a @ w_D1^T   (2048 x 128, K=2048), split-K=8
    {
        dim3 grid(M_ROWS/128, D_DISCR/128, 8);
        mma_gemm<2><<<grid, 256, GSMEM>>>(M_ROWS, D_DISCR, D_MODEL,
                                          a_c, wd1_c, t_p, nullptr, D_MODEL/8);
    }
    // 5b) convert t
    conv(t_p, t_c, M_ROWS, D_DISCR);
    // 6) delta = softplus(D_param + t @ w_D2^T)   (2048 x 2048, K=128)
    {
        dim3 grid(M_ROWS/128, D_MODEL/128, 1);
        mma_gemm<1><<<grid, 256, GSMEM>>>(M_ROWS, D_MODEL, D_DISCR,
                                          t_c, wd2_c, delta_p, D_param, D_DISCR);
    }
    // 7) fused SSM scan + gating -> y_c (packed bf16)
    {
        scan_kernel<<<(B_SZ*D_MODEL)/128, 128>>>(delta_p, a_p, ab_p, Bm_p, Cm_p,
                                                 A_param, D_param, y_c);
    }
    // 8) out = y @ w_out^T  (2048 x 1024, K=2048) -> d_out
    {
        dim3 grid(M_ROWS/128, D_IN/128, 1);
        mma_gemm<0><<<grid, 256, GSMEM>>>(M_ROWS, D_IN, D_MODEL,
                                          y_c, wout_c, out, nullptr, D_MODEL);
    }
}

// round 7
// speedup vs baseline: 5.6806x; 3.6298x over previous
#include <cuda_runtime.h>
#include <cuda_fp16.h>
#include <cstdint>
#include <math.h>

// Problem constants
#define B_SZ 2
#define L_SEQ 1024
#define D_IN 1024
#define D_MODEL 2048
#define D_STATE 16
#define D_DISCR 128
#define KER 4
#define M_ROWS (B_SZ * L_SEQ)          // 2048
#define N_BCT 256                      // padded: 16 B + 16 C + 128 D1 + 96 zero
#define NCHUNK 8
#define LCHUNK (L_SEQ / NCHUNK)        // 128
#define NCHAN (B_SZ * D_MODEL)         // 4096

// ---------------- scratch (device globals; no allocation) ----------------
__device__ float g_ab[(size_t)M_ROWS * 2 * D_MODEL];      // in_proj out [2048,4096]
__device__ float g_a[(size_t)M_ROWS * D_MODEL];           // post conv+silu fp32
__device__ float g_tall[(size_t)M_ROWS * N_BCT];          // [Bm|Cm|t|pad] fp32
__device__ float g_delta[(size_t)M_ROWS * D_MODEL];
__device__ float g_P[(size_t)NCHUNK * NCHAN * D_STATE];   // chunk decay products
__device__ float g_hend[(size_t)NCHUNK * NCHAN * D_STATE];
__device__ float g_hstart[(size_t)NCHUNK * NCHAN * D_STATE];
// fp16 operands
__device__ __half g_seq_h [(size_t)M_ROWS * D_IN];
__device__ __half g_win_h [(size_t)(2*D_MODEL) * D_IN];
__device__ __half g_a_h   [(size_t)M_ROWS * D_MODEL];
__device__ __half g_wbcd_h[(size_t)N_BCT * D_MODEL];
__device__ __half g_wd2_h [(size_t)D_MODEL * D_DISCR];
__device__ __half g_t_h   [(size_t)M_ROWS * D_DISCR];
__device__ __half g_wout_h[(size_t)D_IN * D_MODEL];
__device__ __half g_y_h   [(size_t)M_ROWS * D_MODEL];

// ================= helpers =================
__device__ __forceinline__ uint32_t smem_u32(const void* p) {
    uint32_t a;
    asm("{ .reg .u64 t; cvta.to.shared.u64 t, %1; cvt.u32.u64 %0, t; }" : "=r"(a) : "l"(p));
    return a;
}
__device__ __forceinline__ void ldm4(uint32_t* r, uint32_t addr) {
    asm volatile("ldmatrix.sync.aligned.m8n8.x4.shared.b16 {%0,%1,%2,%3}, [%4];"
                 : "=r"(r[0]), "=r"(r[1]), "=r"(r[2]), "=r"(r[3]) : "r"(addr));
}
__device__ __forceinline__ void mma16816(float* c, const uint32_t* a, const uint32_t* b) {
    asm volatile("mma.sync.aligned.m16n8k16.row.col.f32.f16.f16.f32 "
                 "{%0,%1,%2,%3}, {%4,%5,%6,%7}, {%8,%9}, {%0,%1,%2,%3};"
                 : "+f"(c[0]), "+f"(c[1]), "+f"(c[2]), "+f"(c[3])
                 : "r"(a[0]), "r"(a[1]), "r"(a[2]), "r"(a[3]), "r"(b[0]), "r"(b[1]));
}
__device__ __forceinline__ void cp16(uint32_t dst, const void* src) {
    asm volatile("cp.async.cg.shared.global [%0], [%1], 16;" :: "r"(dst), "l"(src));
}
__device__ __forceinline__ void cp_commit() {
    asm volatile("cp.async.commit_group;" ::: "memory");
}
template<int N>
__device__ __forceinline__ void cp_wait() {
    asm volatile("cp.async.wait_group %0;" :: "n"(N) : "memory");
}
// swizzle for 128B smem rows: XOR 16B-group index with (row & 7)
__device__ __forceinline__ uint32_t swz(int r, int byteCol) {
    uint32_t off = (uint32_t)(r * 128 + byteCol);
    return off ^ (((uint32_t)r & 7u) << 4);
}

// ================= pipelined fp16 HMMA NT GEMM =================
// C[m,n] = sum_k A[m,k]*W[n,k]; A,W row-major fp16 [R][K].
// Block 128x128, BK=64 (128B rows), 256 thr (8 warps 2x4), warp 64x32, 3 stages.
// EPI: 0 plain fp32 store, 1 softplus(bias[n]+v), 2 atomicAdd (split-K).
#define STG 32768
#define NSTG 3
#define GSMEM (NSTG * STG)   // 96 KB

template<int EPI>
__global__ __launch_bounds__(256, 2)
void mma_gemm(int M, int N, int K,
              const __half* __restrict__ A,
              const __half* __restrict__ W,
              float* __restrict__ C,
              const float* __restrict__ bias,
              int kPerSplit)
{
    extern __shared__ char smem[];
    const uint32_t sb = smem_u32(smem);
    const int tid = threadIdx.x;
    const int wid = tid >> 5, lane = tid & 31;
    const int wm = wid & 1, wn = wid >> 1;          // 2 x 4 warp grid
    const int row0 = blockIdx.x * 128;
    const int col0 = blockIdx.y * 128;
    const int k0 = blockIdx.z * kPerSplit;
    const int nCh = kPerSplit / 64;

    const char* Ab = (const char*)A;
    const char* Wb = (const char*)W;

    auto issue = [&](int j) {
        const int st = j % NSTG;
        const uint32_t stA = sb + st * STG;
        const uint32_t stB = stA + 16384;
        const int kt = k0 + j * 64;
#pragma unroll
        for (int i = 0; i < 4; i++) {
            int c = i * 256 + tid;          // 0..1023
            int r = c >> 3, g = c & 7;
            cp16(stA + swz(r, g * 16),
                 Ab + ((size_t)(row0 + r) * K + kt) * 2 + g * 16);
        }
#pragma unroll
        for (int i = 0; i < 4; i++) {
            int c = i * 256 + tid;
            int r = c >> 3, g = c & 7;
            cp16(stB + swz(r, g * 16),
                 Wb + ((size_t)(col0 + r) * K + kt) * 2 + g * 16);
        }
        cp_commit();
    };

    float acc[4][4][4];
#pragma unroll
    for (int i = 0; i < 4; i++)
#pragma unroll
        for (int j = 0; j < 4; j++)
#pragma unroll
            for (int q = 0; q < 4; q++) acc[i][j][q] = 0.f;

    const int pre = (nCh < NSTG - 1) ? nCh : (NSTG - 1);
    for (int j = 0; j < pre; j++) issue(j);

    const int ra_l = (lane & 15);
    const int ga_l = (lane >> 4) * 16;
    const int rb_l = ((lane >> 4) & 1) * 8 + (lane & 7);
    const int gb_l = ((lane >> 3) & 1) * 16;

    for (int j = 0; j < nCh; j++) {
        int newer = nCh - 1 - j; if (newer > NSTG - 2) newer = NSTG - 2;
        if (newer >= 1) cp_wait<1>(); else cp_wait<0>();
        __syncthreads();

        if (j + NSTG - 1 < nCh) issue(j + NSTG - 1);

        const int st = j % NSTG;
        const uint32_t sA = sb + st * STG;
        const uint32_t sB = sA + 16384;

#pragma unroll
        for (int s = 0; s < 4; s++) {
            uint32_t ah[4][4], bh[2][4];
#pragma unroll
            for (int mi = 0; mi < 4; mi++) {
                int r = wm * 64 + mi * 16 + ra_l;
                ldm4(ah[mi], sA + swz(r, s * 32 + ga_l));
            }
#pragma unroll
            for (int p = 0; p < 2; p++) {
                int r = wn * 32 + p * 16 + rb_l;
                ldm4(bh[p], sB + swz(r, s * 32 + gb_l));
            }
#pragma unroll
            for (int mi = 0; mi < 4; mi++) {
#pragma unroll
                for (int ni = 0; ni < 4; ni++) {
                    mma16816(acc[mi][ni], ah[mi], &bh[ni >> 1][(ni & 1) * 2]);
                }
            }
        }
        __syncthreads();
    }

    // ---- epilogue ----
    const int er = (lane >> 2);
    const int ec = (lane & 3) * 2;
#pragma unroll
    for (int mi = 0; mi < 4; mi++) {
#pragma unroll
        for (int ni = 0; ni < 4; ni++) {
            int r = row0 + wm * 64 + mi * 16 + er;
            int c = col0 + wn * 32 + ni * 8 + ec;
            float v0 = acc[mi][ni][0], v1 = acc[mi][ni][1];
            float v2 = acc[mi][ni][2], v3 = acc[mi][ni][3];
            if (EPI == 1) {
                float b0 = bias[c], b1 = bias[c + 1];
                float x;
                x = b0 + v0; v0 = (x > 20.f) ? x : log1pf(expf(x));
                x = b1 + v1; v1 = (x > 20.f) ? x : log1pf(expf(x));
                x = b0 + v2; v2 = (x > 20.f) ? x : log1pf(expf(x));
                x = b1 + v3; v3 = (x > 20.f) ? x : log1pf(expf(x));
            }
            if (EPI == 2) {
                atomicAdd(C + (size_t)r * N + c,           v0);
                atomicAdd(C + (size_t)r * N + c + 1,       v1);
                atomicAdd(C + (size_t)(r + 8) * N + c,     v2);
                atomicAdd(C + (size_t)(r + 8) * N + c + 1, v3);
            } else {
                float2 p0 = {v0, v1}, p1 = {v2, v3};
                *(float2*)(C + (size_t)r * N + c)       = p0;
                *(float2*)(C + (size_t)(r + 8) * N + c) = p1;
            }
        }
    }
}

// ================= converts =================
__global__ void convert_fp16(const float* __restrict__ X, __half* __restrict__ Y, int n)
{
    int idx = blockIdx.x * blockDim.x + threadIdx.x;   // over n/8
    if (idx >= (n >> 3)) return;
    float4 v0 = *(const float4*)(X + (size_t)idx * 8);
    float4 v1 = *(const float4*)(X + (size_t)idx * 8 + 4);
    union { uint4 u; __half h[8]; } o;
    o.h[0] = __float2half_rn(v0.x); o.h[1] = __float2half_rn(v0.y);
    o.h[2] = __float2half_rn(v0.z); o.h[3] = __float2half_rn(v0.w);
    o.h[4] = __float2half_rn(v1.x); o.h[5] = __float2half_rn(v1.y);
    o.h[6] = __float2half_rn(v1.z); o.h[7] = __float2half_rn(v1.w);
    *(uint4*)(Y + (size_t)idx * 8) = o.u;
}

// build padded fused weight [256][2048]: rows 0-15 w_B, 16-31 w_C, 32-159 w_D1, rest 0
__global__ void build_wbcd(const float* __restrict__ wB, const float* __restrict__ wC,
                           const float* __restrict__ wD1, __half* __restrict__ Y)
{
    int idx = blockIdx.x * blockDim.x + threadIdx.x;   // over 256*2048/8
    if (idx >= (N_BCT * D_MODEL) >> 3) return;
    int r = idx / (D_MODEL >> 3);
    int k = (idx % (D_MODEL >> 3)) << 3;
    const float* src = nullptr;
    if (r < 16)       src = wB  + (size_t)r * D_MODEL + k;
    else if (r < 32)  src = wC  + (size_t)(r - 16) * D_MODEL + k;
    else if (r < 160) src = wD1 + (size_t)(r - 32) * D_MODEL + k;
    union { uint4 u; __half h[8]; } o;
    if (src) {
        float4 v0 = *(const float4*)src;
        float4 v1 = *(const float4*)(src + 4);
        o.h[0]=__float2half_rn(v0.x); o.h[1]=__float2half_rn(v0.y);
        o.h[2]=__float2half_rn(v0.z); o.h[3]=__float2half_rn(v0.w);
        o.h[4]=__float2half_rn(v1.x); o.h[5]=__float2half_rn(v1.y);
        o.h[6]=__float2half_rn(v1.z); o.h[7]=__float2half_rn(v1.w);
    } else {
        o.u = make_uint4(0,0,0,0);
    }
    *(uint4*)(Y + (size_t)r * D_MODEL + k) = o.u;
}

// extract t (cols 32..159 of t_all) -> fp16 [2048][128]
__global__ void extract_t(const float* __restrict__ tall, __half* __restrict__ Y)
{
    int idx = blockIdx.x * blockDim.x + threadIdx.x;   // over 2048*128/4
    if (idx >= (M_ROWS * D_DISCR) >> 2) return;
    int r = idx / (D_DISCR >> 2);
    int c = (idx % (D_DISCR >> 2)) << 2;
    float4 v = *(const float4*)(tall + (size_t)r * N_BCT + 32 + c);
    union { uint2 u; __half h[4]; } o;
    o.h[0]=__float2half_rn(v.x); o.h[1]=__float2half_rn(v.y);
    o.h[2]=__float2half_rn(v.z); o.h[3]=__float2half_rn(v.w);
    *(uint2*)(Y + (size_t)r * D_DISCR + c) = o.u;
}

// ------ depthwise causal conv (ker=4) + bias + SiLU -> a fp32 + a_h fp16 ------
__global__ void conv_silu_kernel(const float* __restrict__ ab,
                                 const float* __restrict__ cw,
                                 const float* __restrict__ cb,
                                 float* __restrict__ a_out,
                                 __half* __restrict__ a_h)
{
    int idx = blockIdx.x * blockDim.x + threadIdx.x;
    if (idx >= B_SZ * L_SEQ * D_MODEL) return;
    int d = idx & (D_MODEL - 1);
    int l = (idx >> 11) & (L_SEQ - 1);
    int b = idx >> 21;

    float w0 = cw[d*4+0], w1 = cw[d*4+1], w2 = cw[d*4+2], w3 = cw[d*4+3];
    const size_t rowBase = ((size_t)b * L_SEQ) * (2*D_MODEL);
    float s = cb[d];
    if (l >= 3) s += w0 * ab[rowBase + (size_t)(l-3)*(2*D_MODEL) + d];
    if (l >= 2) s += w1 * ab[rowBase + (size_t)(l-2)*(2*D_MODEL) + d];
    if (l >= 1) s += w2 * ab[rowBase + (size_t)(l-1)*(2*D_MODEL) + d];
    s += w3 * ab[rowBase + (size_t)l*(2*D_MODEL) + d];
    float v = s / (1.f + expf(-s));
    a_out[idx] = v;
    a_h[idx]   = __float2half_rn(v);
}

// ================= chunked scan =================
// phase 1: per (channel, chunk) local scan with h0=0; store decay product P and h_end.
__global__ __launch_bounds__(128)
void scan_phase1(const float* __restrict__ delta,
                 const float* __restrict__ a,
                 const float* __restrict__ tall,
                 const float* __restrict__ A_param,
                 float* __restrict__ Pb,
                 float* __restrict__ hendb)
{
    int gid = blockIdx.x * blockDim.x + threadIdx.x;   // 4096*8
    int ch = gid & (NCHAN - 1);
    int chunk = gid >> 12;
    int b = ch >> 11;
    int d = ch & (D_MODEL - 1);

    float expA[D_STATE];
#pragma unroll
    for (int s = 0; s < D_STATE; s++) expA[s] = expf(-A_param[(size_t)d * D_STATE + s]);

    float h[D_STATE], P[D_STATE];
#pragma unroll
    for (int s = 0; s < D_STATE; s++) { h[s] = 0.f; P[s] = 1.f; }

    const int l0 = chunk * LCHUNK;
    for (int l = l0; l < l0 + LCHUNK; l++) {
        const size_t row = (size_t)b * L_SEQ + l;
        float dlt = delta[row * D_MODEL + d];
        float av  = a[row * D_MODEL + d];
        const float4* Bp = (const float4*)(tall + row * N_BCT);
        float4 B0 = Bp[0], B1 = Bp[1], B2 = Bp[2], B3 = Bp[3];
        float Bv[16] = {B0.x,B0.y,B0.z,B0.w, B1.x,B1.y,B1.z,B1.w,
                        B2.x,B2.y,B2.z,B2.w, B3.x,B3.y,B3.z,B3.w};
        float xc = dlt * av;
#pragma unroll
        for (int s = 0; s < D_STATE; s++) {
            float Ab = expA[s] * dlt;
            h[s] = fmaf(Ab, h[s], Bv[s] * xc);
            P[s] *= Ab;
        }
    }
    float4* Pd = (float4*)(Pb    + ((size_t)chunk * NCHAN + ch) * D_STATE);
    float4* Hd = (float4*)(hendb + ((size_t)chunk * NCHAN + ch) * D_STATE);
#pragma unroll
    for (int q = 0; q < 4; q++) {
        Pd[q] = make_float4(P[q*4], P[q*4+1], P[q*4+2], P[q*4+3]);
        Hd[q] = make_float4(h[q*4], h[q*4+1], h[q*4+2], h[q*4+3]);
    }
}

// phase 2: sequential chunk combine per channel -> h_start per chunk
__global__ __launch_bounds__(128)
void scan_phase2(const float* __restrict__ Pb,
                 const float* __restrict__ hendb,
                 float* __restrict__ hstartb)
{
    int ch = blockIdx.x * blockDim.x + threadIdx.x;    // 4096
    if (ch >= NCHAN) return;
    float hs[D_STATE];
#pragma unroll
    for (int s = 0; s < D_STATE; s++) hs[s] = 0.f;
    for (int c = 0; c < NCHUNK; c++) {
        float4* Hs = (float4*)(hstartb + ((size_t)c * NCHAN + ch) * D_STATE);
#pragma unroll
        for (int q = 0; q < 4; q++)
            Hs[q] = make_float4(hs[q*4], hs[q*4+1], hs[q*4+2], hs[q*4+3]);
        const float4* Pd = (const float4*)(Pb    + ((size_t)c * NCHAN + ch) * D_STATE);
        const float4* He = (const float4*)(hendb + ((size_t)c * NCHAN + ch) * D_STATE);
#pragma unroll
        for (int q = 0; q < 4; q++) {
            float4 p = Pd[q], e = He[q];
            hs[q*4+0] = fmaf(p.x, hs[q*4+0], e.x);
            hs[q*4+1] = fmaf(p.y, hs[q*4+1], e.y);
            hs[q*4+2] = fmaf(p.z, hs[q*4+2], e.z);
            hs[q*4+3] = fmaf(p.w, hs[q*4+3], e.w);
        }
    }
}

// phase 3: re-scan each chunk from h_start, emit y_h = ((h·C) + D*a)*silu(gate)
__global__ __launch_bounds__(128)
void scan_phase3(const float* __restrict__ delta,
                 const float* __restrict__ a,
                 const float* __restrict__ ab,
                 const float* __restrict__ tall,
                 const float* __restrict__ A_param,
                 const float* __restrict__ D_param,
                 const float* __restrict__ hstartb,
                 __half* __restrict__ y_h)
{
    int gid = blockIdx.x * blockDim.x + threadIdx.x;
    int ch = gid & (NCHAN - 1);
    int chunk = gid >> 12;
    int b = ch >> 11;
    int d = ch & (D_MODEL - 1);

    float expA[D_STATE];
#pragma unroll
    for (int s = 0; s < D_STATE; s++) expA[s] = expf(-A_param[(size_t)d * D_STATE + s]);
    const float Dp = D_param[d];

    float h[D_STATE];
    const float4* Hs = (const float4*)(hstartb + ((size_t)chunk * NCHAN + ch) * D_STATE);
#pragma unroll
    for (int q = 0; q < 4; q++) {
        float4 v = Hs[q];
        h[q*4+0] = v.x; h[q*4+1] = v.y; h[q*4+2] = v.z; h[q*4+3] = v.w;
    }

    const int l0 = chunk * LCHUNK;
    for (int l = l0; l < l0 + LCHUNK; l++) {
        const size_t row = (size_t)b * L_SEQ + l;
        float dlt = delta[row * D_MODEL + d];
        float av  = a[row * D_MODEL + d];
        float gt  = ab[row * (2*D_MODEL) + D_MODEL + d];
        const float4* Bp = (const float4*)(tall + row * N_BCT);
        const float4* Cp = (const float4*)(tall + row * N_BCT + 16);
        float4 B0 = Bp[0], B1 = Bp[1], B2 = Bp[2], B3 = Bp[3];
        float4 C0 = Cp[0], C1 = Cp[1], C2 = Cp[2], C3 = Cp[3];
        float Bv[16] = {B0.x,B0.y,B0.z,B0.w, B1.x,B1.y,B1.z,B1.w,
                        B2.x,B2.y,B2.z,B2.w, B3.x,B3.y,B3.z,B3.w};
        float Cv[16] = {C0.x,C0.y,C0.z,C0.w, C1.x,C1.y,C1.z,C1.w,
                        C2.x,C2.y,C2.z,C2.w, C3.x,C3.y,C3.z,C3.w};
        float xc = dlt * av;
        float acc0 = 0.f, acc1 = 0.f;
#pragma unroll
        for (int s = 0; s < D_STATE; s += 2) {
            float Ab0 = expA[s]   * dlt;
            float Ab1 = expA[s+1] * dlt;
            h[s]   = fmaf(Ab0, h[s],   Bv[s]   * xc);
            h[s+1] = fmaf(Ab1, h[s+1], Bv[s+1] * xc);
            acc0   = fmaf(h[s],   Cv[s],   acc0);
            acc1   = fmaf(h[s+1], Cv[s+1], acc1);
        }
        float silu_g = gt / (1.f + expf(-gt));
        float yv = (acc0 + acc1 + Dp * av) * silu_g;
        y_h[row * D_MODEL + d] = __float2half_rn(yv);
    }
}

// ---------------- launch ----------------
extern "C" void kernel_launch(void* const* d_in, const int* in_sizes, int n_in,
                              void* d_out, int out_size)
{
    const float* seq     = (const float*)d_in[0];
    const float* w_in    = (const float*)d_in[1];
    const float* w_out   = (const float*)d_in[2];
    const float* w_B     = (const float*)d_in[3];
    const float* w_C     = (const float*)d_in[4];
    const float* w_D1    = (const float*)d_in[5];
    const float* w_D2    = (const float*)d_in[6];
    const float* conv_w  = (const float*)d_in[7];
    const float* conv_b  = (const float*)d_in[8];
    const float* A_param = (const float*)d_in[9];
    const float* D_param = (const float*)d_in[10];
    float* out = (float*)d_out;

    float *ab_p, *a_p, *tall_p, *delta_p, *P_p, *hend_p, *hstart_p;
    __half *seq_h, *win_h, *a_h, *wbcd_h, *wd2_h, *t_h, *wout_h, *y_h;
    cudaGetSymbolAddress((void**)&ab_p,    g_ab);
    cudaGetSymbolAddress((void**)&a_p,     g_a);
    cudaGetSymbolAddress((void**)&tall_p,  g_tall);
    cudaGetSymbolAddress((void**)&delta_p, g_delta);
    cudaGetSymbolAddress((void**)&P_p,     g_P);
    cudaGetSymbolAddress((void**)&hend_p,  g_hend);
    cudaGetSymbolAddress((void**)&hstart_p,g_hstart);
    cudaGetSymbolAddress((void**)&seq_h,   g_seq_h);
    cudaGetSymbolAddress((void**)&win_h,   g_win_h);
    cudaGetSymbolAddress((void**)&a_h,     g_a_h);
    cudaGetSymbolAddress((void**)&wbcd_h,  g_wbcd_h);
    cudaGetSymbolAddress((void**)&wd2_h,   g_wd2_h);
    cudaGetSymbolAddress((void**)&t_h,     g_t_h);
    cudaGetSymbolAddress((void**)&wout_h,  g_wout_h);
    cudaGetSymbolAddress((void**)&y_h,     g_y_h);

    cudaFuncSetAttribute(mma_gemm<0>, cudaFuncAttributeMaxDynamicSharedMemorySize, GSMEM);
    cudaFuncSetAttribute(mma_gemm<1>, cudaFuncAttributeMaxDynamicSharedMemorySize, GSMEM);
    cudaFuncSetAttribute(mma_gemm<2>, cudaFuncAttributeMaxDynamicSharedMemorySize, GSMEM);

    auto cvt = [&](const float* X, __half* Y, int n) {
        convert_fp16<<<((n >> 3) + 255)/256, 256>>>(X, Y, n);
    };

    // 0) convert inputs / weights to fp16
    cvt(seq,   seq_h,  M_ROWS * D_IN);
    cvt(w_in,  win_h,  2*D_MODEL * D_IN);
    cvt(w_D2,  wd2_h,  D_MODEL * D_DISCR);
    cvt(w_out, wout_h, D_IN * D_MODEL);
    build_wbcd<<<((N_BCT*D_MODEL >> 3) + 255)/256, 256>>>(w_B, w_C, w_D1, wbcd_h);

    // 1) in_proj: ab = seq @ w_in^T   (2048 x 4096, K=1024)
    {
        dim3 grid(M_ROWS/128, (2*D_MODEL)/128, 1);
        mma_gemm<0><<<grid, 256, GSMEM>>>(M_ROWS, 2*D_MODEL, D_IN,
                                          seq_h, win_h, ab_p, nullptr, D_IN);
    }
    // 2) depthwise conv + bias + silu -> a fp32 + a_h fp16
    {
        int n = B_SZ * L_SEQ * D_MODEL;
        conv_silu_kernel<<<(n + 255)/256, 256>>>(ab_p, conv_w, conv_b, a_p, a_h);
    }
    // 3) fused BCt: t_all = a @ [w_B|w_C|w_D1|0]^T  (2048 x 256, K=2048), split-K=4
    cudaMemsetAsync(tall_p, 0, (size_t)M_ROWS * N_BCT * sizeof(float));
    {
        dim3 grid(M_ROWS/128, N_BCT/128, 4);
        mma_gemm<2><<<grid, 256, GSMEM>>>(M_ROWS, N_BCT, D_MODEL,
                                          a_h, wbcd_h, tall_p, nullptr, D_MODEL/4);
    }
    // 4) t -> fp16
    extract_t<<<((M_ROWS*D_DISCR >> 2) + 255)/256, 256>>>(tall_p, t_h);
    // 5) delta = softplus(D_param + t @ w_D2^T)   (2048 x 2048, K=128)
    {
        dim3 grid(M_ROWS/128, D_MODEL/128, 1);
        mma_gemm<1><<<grid, 256, GSMEM>>>(M_ROWS, D_MODEL, D_DISCR,
                                          t_h, wd2_h, delta_p, D_param, D_DISCR);
    }
    // 6) chunked scan
    scan_phase1<<<(NCHAN*NCHUNK)/128, 128>>>(delta_p, a_p, tall_p, A_param, P_p, hend_p);
    scan_phase2<<<NCHAN/128, 128>>>(P_p, hend_p, hstart_p);
    scan_phase3<<<(NCHAN*NCHUNK)/128, 128>>>(delta_p, a_p, ab_p, tall_p,
                                             A_param, D_param, hstart_p, y_h);
    // 7) out = y @ w_out^T  (2048 x 1024, K=2048) -> d_out
    {
        dim3 grid(M_ROWS/128, D_IN/128, 1);
        mma_gemm<0><<<grid, 256, GSMEM>>>(M_ROWS, D_IN, D_MODEL,
                                          y_h, wout_h, out, nullptr, D_MODEL);
    }
}